// round 11
// baseline (speedup 1.0000x reference)
#include <cuda_runtime.h>
#include <cstdint>

#define N_NODES  100000
#define N_EDGES  1600000
#define D        128
#define N_LAYERS 7
#define N_GRAPHS 64
#define N_CLASSES 10
#define SNN_IN   512
#define SNN_HID  1024
#define SNN_BETA 0.85f

// ---------------- scratch (no allocations allowed) ----------------
__device__ float g_h0[N_NODES * D];
__device__ float g_h1[N_NODES * D];
__device__ float g_agg[N_NODES * D];
__device__ int   g_counts[N_NODES];
__device__ int   g_rowptr[N_NODES + 1];
__device__ int   g_wptr[N_NODES];
__device__ int   g_esrc[N_EDGES];
__device__ int   g_blocksums[256];
__device__ float g_pool[N_GRAPHS * D];
__device__ float g_cnt[N_GRAPHS];
__device__ float g_snnh[N_GRAPHS * SNN_HID];
__device__ int   g_flags[2];   // [0]: edge_index is int64, [1]: batch is int64
// int8 2-digit quantized weights: [l][mat][digit][n][kword] (4 k per 32-bit word)
__device__ uint32_t g_wq[N_LAYERS * 2 * 2 * D * (D / 4)];
__device__ float g_cscale[N_LAYERS * D];   // colmax/127
__device__ float g_cinv[N_LAYERS * D];     // 127/colmax
__device__ float g_rscale[N_NODES + 512];  // rowmax/127 (concat [agg|h] row)
__device__ float g_rinv[N_NODES + 512];    // 127/rowmax
__device__ float g_hmax0[N_NODES];         // row max of h, cols 0..63
__device__ float g_hmax1[N_NODES];         // row max of h, cols 64..127

// ---------------- portable tensor-core helpers (sm_80+ ISA only) ----------------
__device__ __forceinline__ void mma_s8(int* d, const uint32_t* a, uint32_t b0, uint32_t b1) {
    asm volatile(
        "mma.sync.aligned.m16n8k32.row.col.s32.s8.s8.s32 "
        "{%0,%1,%2,%3}, {%4,%5,%6,%7}, {%8,%9}, {%0,%1,%2,%3};"
        : "+r"(d[0]), "+r"(d[1]), "+r"(d[2]), "+r"(d[3])
        : "r"(a[0]), "r"(a[1]), "r"(a[2]), "r"(a[3]), "r"(b0), "r"(b1));
}
__device__ __forceinline__ void ldsm_x4(uint32_t* r, uint32_t addr) {
    asm volatile("ldmatrix.sync.aligned.m8n8.x4.shared.b16 {%0,%1,%2,%3}, [%4];"
        : "=r"(r[0]), "=r"(r[1]), "=r"(r[2]), "=r"(r[3]) : "r"(addr));
}
__device__ __forceinline__ void ldsm_x2(uint32_t* r, uint32_t addr) {
    asm volatile("ldmatrix.sync.aligned.m8n8.x2.shared.b16 {%0,%1}, [%2];"
        : "=r"(r[0]), "=r"(r[1]) : "r"(addr));
}
__device__ __forceinline__ uint32_t smem_u32(const void* p) {
    uint32_t a;
    asm("{ .reg .u64 t; cvta.to.shared.u64 t, %1; cvt.u32.u64 %0, t; }" : "=r"(a) : "l"(p));
    return a;
}
// quantize one float to two s8 digits: v*inv ~= i1 + i2/128
__device__ __forceinline__ void quant2(float v, float inv, int& i1, int& i2) {
    float f = fminf(fmaxf(v * inv, -127.f), 127.f);
    i1 = __float2int_rn(f);
    i2 = __float2int_rn((f - (float)i1) * 128.f);
}

// ---------------- index-width helpers ----------------
__device__ __forceinline__ int ld_idx(const void* p, long long i, int is64) {
    if (is64) return (int)((const long long*)p)[i];
    return ((const int*)p)[i];
}

// Parallel dtype detection
__global__ void k_detect(const unsigned int* ei, const unsigned int* bt) {
    __shared__ int e64s, b64s;
    int t = threadIdx.x;   // 256
    if (t == 0) { e64s = 1; b64s = 1; }
    __syncthreads();
    if (ei[2 * t + 1] != 0u) e64s = 0;
    if (bt[99999 - 2 * t] != 0u) b64s = 0;
    __syncthreads();
    if (t == 0) { g_flags[0] = e64s; g_flags[1] = b64s; }
}

// per-column weight scales over concat [W1;W2] column (256 values)
__global__ void k_wscale(const float* __restrict__ wrel, const float* __restrict__ wroot) {
    int widx = (blockIdx.x * blockDim.x + threadIdx.x) >> 5;
    int lane = threadIdx.x & 31;
    if (widx >= N_LAYERS * D) return;
    int l = widx / D;
    int n = widx % D;
    float m = 0.f;
    for (int j = 0; j < 4; j++) {
        int k = lane + 32 * j;
        m = fmaxf(m, fabsf(wrel[(long long)l * D * D + k * D + n]));
        m = fmaxf(m, fabsf(wroot[(long long)l * D * D + k * D + n]));
    }
    for (int off = 16; off > 0; off >>= 1)
        m = fmaxf(m, __shfl_xor_sync(0xffffffffu, m, off));
    if (lane == 0) {
        g_cscale[widx] = m * (1.f / 127.f);
        g_cinv[widx] = (m > 0.f) ? 127.f / m : 0.f;
    }
}

// transpose + 2-digit int8 quantize weights, 4 k per word
__global__ void k_wprep(const float* __restrict__ wrel, const float* __restrict__ wroot) {
    int idx = blockIdx.x * 256 + threadIdx.x;
    const int WORDS = N_LAYERS * 2 * D * (D / 4);   // 57344
    if (idx >= WORDS) return;
    int l = idx / 8192;
    int rem = idx % 8192;
    int mat = rem >> 12;
    int r2 = rem & 4095;
    int n = r2 >> 5;
    int w4 = r2 & 31;
    const float* W = (mat ? wroot : wrel) + (long long)l * D * D;
    float cinv = g_cinv[l * D + n];
    uint32_t w1 = 0, w2 = 0;
#pragma unroll
    for (int j = 0; j < 4; j++) {
        int i1, i2;
        quant2(W[(w4 * 4 + j) * D + n], cinv, i1, i2);
        w1 |= (uint32_t)(i1 & 0xFF) << (8 * j);
        w2 |= (uint32_t)(i2 & 0xFF) << (8 * j);
    }
    int base = ((l * 2 + mat) * 2) * 4096 + n * 32 + w4;
    g_wq[base] = w1;
    g_wq[base + 4096] = w2;
}

// row max of |x| for layer-0 h part
__global__ void k_rowmax0(const float* __restrict__ x) {
    int node = (blockIdx.x * blockDim.x + threadIdx.x) >> 5;
    int lane = threadIdx.x & 31;
    if (node >= N_NODES) return;
    float4 v = *(const float4*)&x[(long long)node * D + lane * 4];
    float m = fmaxf(fmaxf(fabsf(v.x), fabsf(v.y)), fmaxf(fabsf(v.z), fabsf(v.w)));
    for (int off = 16; off > 0; off >>= 1)
        m = fmaxf(m, __shfl_xor_sync(0xffffffffu, m, off));
    if (lane == 0) { g_hmax0[node] = m; g_hmax1[node] = 0.f; }
}

// ---------------- CSR build ----------------
__global__ void k_zero_counts() {
    int i = blockIdx.x * blockDim.x + threadIdx.x;
    if (i < N_NODES) g_counts[i] = 0;
}
__global__ void k_hist(const void* ei) {
    int e = blockIdx.x * blockDim.x + threadIdx.x;
    if (e >= N_EDGES) return;
    int dst = ld_idx(ei, (long long)N_EDGES + e, g_flags[0]);
    atomicAdd(&g_counts[dst], 1);
}
__global__ void k_scan1() {
    __shared__ int s[1024];
    int blk = blockIdx.x, t = threadIdx.x;
    int idx = blk * 1024 + t;
    int v = (idx < N_NODES) ? g_counts[idx] : 0;
    s[t] = v;
    __syncthreads();
    for (int off = 1; off < 1024; off <<= 1) {
        int add = (t >= off) ? s[t - off] : 0;
        __syncthreads();
        s[t] += add;
        __syncthreads();
    }
    if (idx < N_NODES) g_rowptr[idx] = s[t];
    if (t == 1023) g_blocksums[blk] = s[t];
}
__global__ void k_scan2(int nblocks) {
    if (blockIdx.x == 0 && threadIdx.x == 0) {
        int acc = 0;
        for (int b = 0; b < nblocks; b++) { int v = g_blocksums[b]; g_blocksums[b] = acc; acc += v; }
        g_rowptr[N_NODES] = N_EDGES;
    }
}
__global__ void k_scan3() {
    int i = blockIdx.x * blockDim.x + threadIdx.x;
    if (i < N_NODES) {
        int ex = g_rowptr[i] - g_counts[i] + g_blocksums[i >> 10];
        g_rowptr[i] = ex;
        g_wptr[i] = ex;
    }
}
__global__ void k_scatter(const void* ei) {
    int e = blockIdx.x * blockDim.x + threadIdx.x;
    if (e >= N_EDGES) return;
    int is64 = g_flags[0];
    int src = ld_idx(ei, e, is64);
    int dst = ld_idx(ei, (long long)N_EDGES + e, is64);
    int pos = atomicAdd(&g_wptr[dst], 1);
    g_esrc[pos] = src;
}

// ---------------- aggregation: warp per node + row-scale production ----------------
__global__ void k_agg(const float* __restrict__ h, float* __restrict__ agg) {
    int node = (blockIdx.x * blockDim.x + threadIdx.x) >> 5;
    int lane = threadIdx.x & 31;
    if (node >= N_NODES) return;
    int s = g_rowptr[node];
    int e = g_rowptr[node + 1];
    float4 a0 = make_float4(0.f, 0.f, 0.f, 0.f);
    float4 a1 = make_float4(0.f, 0.f, 0.f, 0.f);
    int i = s;
    for (; i + 4 <= e; i += 4) {
        int s0 = g_esrc[i];
        int s1 = g_esrc[i + 1];
        int s2 = g_esrc[i + 2];
        int s3 = g_esrc[i + 3];
        float4 v0 = *(const float4*)&h[(long long)s0 * D + lane * 4];
        float4 v1 = *(const float4*)&h[(long long)s1 * D + lane * 4];
        float4 v2 = *(const float4*)&h[(long long)s2 * D + lane * 4];
        float4 v3 = *(const float4*)&h[(long long)s3 * D + lane * 4];
        a0.x += v0.x; a0.y += v0.y; a0.z += v0.z; a0.w += v0.w;
        a1.x += v1.x; a1.y += v1.y; a1.z += v1.z; a1.w += v1.w;
        a0.x += v2.x; a0.y += v2.y; a0.z += v2.z; a0.w += v2.w;
        a1.x += v3.x; a1.y += v3.y; a1.z += v3.z; a1.w += v3.w;
    }
    for (; i < e; i++) {
        int s0 = g_esrc[i];
        float4 v0 = *(const float4*)&h[(long long)s0 * D + lane * 4];
        a0.x += v0.x; a0.y += v0.y; a0.z += v0.z; a0.w += v0.w;
    }
    a0.x += a1.x; a0.y += a1.y; a0.z += a1.z; a0.w += a1.w;
    *(float4*)&agg[(long long)node * D + lane * 4] = a0;
    // row scale over concat [agg | h]
    float lm = fmaxf(fmaxf(fabsf(a0.x), fabsf(a0.y)), fmaxf(fabsf(a0.z), fabsf(a0.w)));
    for (int off = 16; off > 0; off >>= 1)
        lm = fmaxf(lm, __shfl_xor_sync(0xffffffffu, lm, off));
    if (lane == 0) {
        float m = fmaxf(lm, fmaxf(g_hmax0[node], g_hmax1[node]));
        if (m > 0.f) {
            g_rinv[node] = 127.f / m;
            g_rscale[node] = m * (1.f / 127.f);
        } else {
            g_rinv[node] = 0.f;
            g_rscale[node] = 0.f;
        }
    }
}

// ---------------- 2-digit int8 mma GraphConv GEMM (double-buffered) ----------------
// C = relu( rs * cs * [ acc11 + accX/128 ] + bias ), acc over concat K=256.
// SMEM tiles: 128 rows x 32 s8 per digit plane, row stride 48B (conflict-free).
#define QSTR 48
#define SM_Q1 0
#define SM_Q2 6144
#define SM_B1 12288
#define SM_B2 18432
#define BUFSZ 24576
#define GEMM_SMEM (2 * BUFSZ)

__global__ __launch_bounds__(256, 1)
void k_gemm_s8(const float* __restrict__ A1, const float* __restrict__ A2,
               const uint32_t* __restrict__ Wt,     // layer base: 4 planes of 4096 words
               const float* __restrict__ csc,       // per-col scale (this layer)
               const float* __restrict__ bias, float* __restrict__ C) {
    extern __shared__ __align__(16) char smc[];
    const uint32_t sbase = smem_u32(smc);
    const int tid = threadIdx.x;
    const int w = tid >> 5;
    const int lane = tid & 31;
    const int g = lane >> 2;
    const int tg = lane & 3;
    const int bm = blockIdx.x * 128;
    const int mbase = (w & 3) * 32;
    const int nbase = (w >> 2) * 64;

    int acc11[2][8][4], accX[2][8][4];
#pragma unroll
    for (int mt = 0; mt < 2; mt++)
#pragma unroll
        for (int nt = 0; nt < 8; nt++)
#pragma unroll
            for (int q = 0; q < 4; q++) { acc11[mt][nt][q] = 0; accX[mt][nt][q] = 0; }

    const int srow = tid >> 3;          // 0..31, +32 per it
    const int sq = tid & 7;             // k-word (4 k values)

    // row inv-scales for the 4 staged rows (fixed across chunks)
    float rv[4];
#pragma unroll
    for (int it = 0; it < 4; it++) {
        int row = bm + it * 32 + srow;
        rv[it] = (row < N_NODES) ? g_rinv[row] : 0.f;
    }

    // ---- prologue: load + stage chunk 0 (A from agg, W1) into buf0 ----
    float4 pa[4];
#pragma unroll
    for (int it = 0; it < 4; it++) {
        int row = it * 32 + srow;
        pa[it] = (bm + row < N_NODES)
                 ? *(const float4*)&A1[(long long)(bm + row) * 128 + sq * 4]
                 : make_float4(0.f, 0.f, 0.f, 0.f);
    }
#pragma unroll
    for (int it = 0; it < 4; it++) {
        int row = it * 32 + srow;
        uint32_t off = (uint32_t)(row * QSTR + sq * 4);
        float4 v = pa[it];
        int i1, i2;
        uint32_t w1 = 0, w2 = 0;
        quant2(v.x, rv[it], i1, i2); w1 |= (uint32_t)(i1 & 0xFF);       w2 |= (uint32_t)(i2 & 0xFF);
        quant2(v.y, rv[it], i1, i2); w1 |= (uint32_t)(i1 & 0xFF) << 8;  w2 |= (uint32_t)(i2 & 0xFF) << 8;
        quant2(v.z, rv[it], i1, i2); w1 |= (uint32_t)(i1 & 0xFF) << 16; w2 |= (uint32_t)(i2 & 0xFF) << 16;
        quant2(v.w, rv[it], i1, i2); w1 |= (uint32_t)(i1 & 0xFF) << 24; w2 |= (uint32_t)(i2 & 0xFF) << 24;
        *(uint32_t*)(smc + SM_Q1 + off) = w1;
        *(uint32_t*)(smc + SM_Q2 + off) = w2;
        *(uint32_t*)(smc + SM_B1 + off) = Wt[row * 32 + sq];
        *(uint32_t*)(smc + SM_B2 + off) = Wt[4096 + row * 32 + sq];
    }
    __syncthreads();
#pragma unroll
    for (int it = 0; it < 4; it++) {
        int row = it * 32 + srow;
        pa[it] = (bm + row < N_NODES)
                 ? *(const float4*)&A1[(long long)(bm + row) * 128 + 32 + sq * 4]
                 : make_float4(0.f, 0.f, 0.f, 0.f);
    }

    // ldmatrix lane addressing (b16-unit congruence: 1 unit = 2 s8 along k)
    const int aRow16 = lane & 15;
    const uint32_t aSel = (uint32_t)(lane >> 4) * 16u;
    const int bRow = lane & 7;
    const uint32_t bK = (uint32_t)((lane >> 3) & 1) * 16u;

#pragma unroll
    for (int c = 0; c < 8; c++) {
        const uint32_t curB = (uint32_t)(c & 1) * BUFSZ;
        const uint32_t nxtB = curB ^ BUFSZ;

        // ---- stage chunk c+1 into buf[nxt] ----
        if (c < 7) {
            const int cn = c + 1;
            const int kw0 = (cn & 3) * 8;
            const uint32_t* B1p = Wt + ((cn >> 2) * 2) * 4096;
            const uint32_t* B2p = B1p + 4096;
#pragma unroll
            for (int it = 0; it < 4; it++) {
                int row = it * 32 + srow;
                uint32_t off = nxtB + (uint32_t)(row * QSTR + sq * 4);
                float4 v = pa[it];
                int i1, i2;
                uint32_t w1 = 0, w2 = 0;
                quant2(v.x, rv[it], i1, i2); w1 |= (uint32_t)(i1 & 0xFF);       w2 |= (uint32_t)(i2 & 0xFF);
                quant2(v.y, rv[it], i1, i2); w1 |= (uint32_t)(i1 & 0xFF) << 8;  w2 |= (uint32_t)(i2 & 0xFF) << 8;
                quant2(v.z, rv[it], i1, i2); w1 |= (uint32_t)(i1 & 0xFF) << 16; w2 |= (uint32_t)(i2 & 0xFF) << 16;
                quant2(v.w, rv[it], i1, i2); w1 |= (uint32_t)(i1 & 0xFF) << 24; w2 |= (uint32_t)(i2 & 0xFF) << 24;
                *(uint32_t*)(smc + SM_Q1 + off) = w1;
                *(uint32_t*)(smc + SM_Q2 + off) = w2;
                *(uint32_t*)(smc + SM_B1 + off) = B1p[row * 32 + kw0 + sq];
                *(uint32_t*)(smc + SM_B2 + off) = B2p[row * 32 + kw0 + sq];
            }
        }
        // ---- prefetch chunk c+2's A ----
        if (c < 6) {
            const int cn2 = c + 2;
            const float* An = (cn2 < 4) ? A1 : A2;
            const int k0n = (cn2 & 3) * 32;
#pragma unroll
            for (int it = 0; it < 4; it++) {
                int row = it * 32 + srow;
                pa[it] = (bm + row < N_NODES)
                         ? *(const float4*)&An[(long long)(bm + row) * 128 + k0n + sq * 4]
                         : make_float4(0.f, 0.f, 0.f, 0.f);
            }
        }

        // ---- compute chunk c: one k32 step ----
        uint32_t a1f[2][4], a2f[2][4];
#pragma unroll
        for (int mt = 0; mt < 2; mt++) {
            uint32_t base = sbase + curB + (uint32_t)((mbase + mt * 16 + aRow16) * QSTR) + aSel;
            ldsm_x4(a1f[mt], base + SM_Q1);
            ldsm_x4(a2f[mt], base + SM_Q2);
        }
#pragma unroll
        for (int nt = 0; nt < 8; nt++) {
            uint32_t bb = sbase + curB + (uint32_t)((nbase + nt * 8 + bRow) * QSTR) + bK;
            uint32_t b1[2], b2[2];
            ldsm_x2(b1, bb + SM_B1);
            ldsm_x2(b2, bb + SM_B2);
#pragma unroll
            for (int mt = 0; mt < 2; mt++) {
                mma_s8(acc11[mt][nt], a1f[mt], b1[0], b1[1]);
                mma_s8(accX[mt][nt], a1f[mt], b2[0], b2[1]);
                mma_s8(accX[mt][nt], a2f[mt], b1[0], b1[1]);
            }
        }
        __syncthreads();
    }

    // ---- epilogue: dequant + bias + relu + next-layer row max ----
    float* hma = (w >> 2) ? g_hmax1 : g_hmax0;
#pragma unroll
    for (int mt = 0; mt < 2; mt++) {
        int row0 = bm + mbase + mt * 16 + g;
        int row1 = row0 + 8;
        float rs0 = (row0 < N_NODES) ? g_rscale[row0] : 0.f;
        float rs1 = (row1 < N_NODES) ? g_rscale[row1] : 0.f;
        float m0 = 0.f, m1 = 0.f;
#pragma unroll
        for (int nt = 0; nt < 8; nt++) {
            int col = nbase + nt * 8 + 2 * tg;
            float cs0 = csc[col];
            float cs1 = csc[col + 1];
            float b0 = bias[col];
            float b1 = bias[col + 1];
            float a0 = (float)acc11[mt][nt][0] + (float)accX[mt][nt][0] * 0.0078125f;
            float a1 = (float)acc11[mt][nt][1] + (float)accX[mt][nt][1] * 0.0078125f;
            float a2 = (float)acc11[mt][nt][2] + (float)accX[mt][nt][2] * 0.0078125f;
            float a3 = (float)acc11[mt][nt][3] + (float)accX[mt][nt][3] * 0.0078125f;
            if (row0 < N_NODES) {
                float2 o;
                o.x = fmaxf(fmaf(a0, rs0 * cs0, b0), 0.f);
                o.y = fmaxf(fmaf(a1, rs0 * cs1, b1), 0.f);
                *(float2*)&C[(long long)row0 * 128 + col] = o;
                m0 = fmaxf(m0, fmaxf(o.x, o.y));
            }
            if (row1 < N_NODES) {
                float2 o;
                o.x = fmaxf(fmaf(a2, rs1 * cs0, b0), 0.f);
                o.y = fmaxf(fmaf(a3, rs1 * cs1, b1), 0.f);
                *(float2*)&C[(long long)row1 * 128 + col] = o;
                m1 = fmaxf(m1, fmaxf(o.x, o.y));
            }
        }
        m0 = fmaxf(m0, __shfl_xor_sync(0xffffffffu, m0, 1));
        m0 = fmaxf(m0, __shfl_xor_sync(0xffffffffu, m0, 2));
        m1 = fmaxf(m1, __shfl_xor_sync(0xffffffffu, m1, 1));
        m1 = fmaxf(m1, __shfl_xor_sync(0xffffffffu, m1, 2));
        if (tg == 0) {
            if (row0 < N_NODES) hma[row0] = m0;
            if (row1 < N_NODES) hma[row1] = m1;
        }
    }
}

// ---------------- pooling / SNN / fusion ----------------
__global__ void k_zero_pool() {
    int i = blockIdx.x * blockDim.x + threadIdx.x;
    if (i < N_GRAPHS * D) g_pool[i] = 0.f;
    if (i < N_GRAPHS) g_cnt[i] = 0.f;
}

#define PCHUNK 256
__global__ void k_pool(const float* __restrict__ h, const void* bt) {
    int blk = blockIdx.x;
    int f = threadIdx.x;
    int start = blk * PCHUNK;
    if (start >= N_NODES) return;
    int end = start + PCHUNK;
    if (end > N_NODES) end = N_NODES;
    int is64 = g_flags[1];
    int cur = ld_idx(bt, start, is64);
    float s = 0.f, c = 0.f;
    for (int n = start; n < end; n++) {
        int g = ld_idx(bt, n, is64);
        if (g != cur) {
            atomicAdd(&g_pool[cur * D + f], s);
            if (f == 0) atomicAdd(&g_cnt[cur], c);
            s = 0.f; c = 0.f; cur = g;
        }
        s += h[(long long)n * D + f];
        c += 1.f;
    }
    atomicAdd(&g_pool[cur * D + f], s);
    if (f == 0) atomicAdd(&g_cnt[cur], c);
}

__global__ void k_snn1(const float* __restrict__ x, const float* __restrict__ w1,
                       const float* __restrict__ b1) {
    int g = blockIdx.x;
    int t = threadIdx.x;   // 256
    __shared__ float xs[SNN_IN];
    for (int i = t; i < SNN_IN; i += 256) xs[i] = x[g * SNN_IN + i];
    __syncthreads();
    for (int j = t; j < SNN_HID; j += 256) {
        float a = b1[j];
        for (int k = 0; k < SNN_IN; k++)
            a += xs[k] * w1[k * SNN_HID + j];
        g_snnh[g * SNN_HID + j] = fmaxf(a, 0.f);
    }
}

__global__ void k_final(const float* __restrict__ lin_w, const float* __restrict__ lin_b,
                        const float* __restrict__ w2, const float* __restrict__ b2,
                        const float* __restrict__ fuse_w, const float* __restrict__ fuse_b,
                        float* __restrict__ out) {
    int g = blockIdx.x;
    int t = threadIdx.x;   // 128
    __shared__ float mean[D];
    __shared__ float red[128];
    __shared__ float snl[N_CLASSES], gnl[N_CLASSES];
    float cnt = fmaxf(g_cnt[g], 1.f);
    mean[t] = g_pool[g * D + t] / cnt;
    __syncthreads();
    for (int c = 0; c < N_CLASSES; c++) {
        red[t] = mean[t] * lin_w[t * N_CLASSES + c];
        for (int off = 64; off > 0; off >>= 1) {
            __syncthreads();
            if (t < off) red[t] += red[t + off];
        }
        __syncthreads();
        if (t == 0) gnl[c] = red[0] + lin_b[c];
        __syncthreads();
    }
    for (int c = 0; c < N_CLASSES; c++) {
        float p = 0.f;
        for (int k = t; k < SNN_HID; k += 128)
            p += g_snnh[g * SNN_HID + k] * w2[k * N_CLASSES + c];
        red[t] = p;
        for (int off = 64; off > 0; off >>= 1) {
            __syncthreads();
            if (t < off) red[t] += red[t + off];
        }
        __syncthreads();
        if (t == 0) snl[c] = SNN_BETA * (red[0] + b2[c]);
        __syncthreads();
    }
    if (t < N_CLASSES) {
        float o = fuse_b[t];
        for (int j = 0; j < N_CLASSES; j++) {
            o += snl[j] * fuse_w[j * N_CLASSES + t];
            o += gnl[j] * fuse_w[(N_CLASSES + j) * N_CLASSES + t];
        }
        out[g * N_CLASSES + t] = o;
    }
}

// ---------------- launch ----------------
extern "C" void kernel_launch(void* const* d_in, const int* in_sizes, int n_in,
                              void* d_out, int out_size) {
    const float* snn_x  = (const float*)d_in[0];
    const float* x      = (const float*)d_in[1];
    const void*  ei     = d_in[2];
    const void*  bt     = d_in[3];
    const float* snn_w1 = (const float*)d_in[4];
    const float* snn_b1 = (const float*)d_in[5];
    const float* snn_w2 = (const float*)d_in[6];
    const float* snn_b2 = (const float*)d_in[7];
    const float* wrel   = (const float*)d_in[8];
    const float* wroot  = (const float*)d_in[9];
    const float* brel   = (const float*)d_in[10];
    const float* lin_w  = (const float*)d_in[11];
    const float* lin_b  = (const float*)d_in[12];
    const float* fuse_w = (const float*)d_in[13];
    const float* fuse_b = (const float*)d_in[14];
    float* out = (float*)d_out;

    void* p;
    cudaGetSymbolAddress(&p, g_h0);      float* h0  = (float*)p;
    cudaGetSymbolAddress(&p, g_h1);      float* h1  = (float*)p;
    cudaGetSymbolAddress(&p, g_agg);     float* agp = (float*)p;
    cudaGetSymbolAddress(&p, g_wq);      uint32_t* wq = (uint32_t*)p;
    cudaGetSymbolAddress(&p, g_cscale);  float* csc = (float*)p;

    cudaFuncSetAttribute(k_gemm_s8, cudaFuncAttributeMaxDynamicSharedMemorySize, GEMM_SMEM);

    k_detect<<<1, 256>>>((const unsigned int*)ei, (const unsigned int*)bt);
    k_wscale<<<(N_LAYERS * D * 32 + 255) / 256, 256>>>(wrel, wroot);
    k_wprep<<<(N_LAYERS * 2 * D * (D / 4) + 255) / 256, 256>>>(wrel, wroot);
    k_rowmax0<<<(N_NODES * 32 + 255) / 256, 256>>>(x);

    // CSR build (by dst)
    k_zero_counts<<<(N_NODES + 255) / 256, 256>>>();
    k_hist<<<(N_EDGES + 255) / 256, 256>>>(ei);
    const int nsb = (N_NODES + 1023) / 1024;   // 98
    k_scan1<<<nsb, 1024>>>();
    k_scan2<<<1, 1>>>(nsb);
    k_scan3<<<(N_NODES + 255) / 256, 256>>>();
    k_scatter<<<(N_EDGES + 255) / 256, 256>>>(ei);

    // 7 GraphConv layers; layer 0 consumes x directly
    const float* hin = x;
    float* hout = h1;
    const int aggBlocks = (N_NODES * 32 + 255) / 256;
    const int gemmBlocks = (N_NODES + 127) / 128;   // 782
    for (int l = 0; l < N_LAYERS; l++) {
        k_agg<<<aggBlocks, 256>>>(hin, agp);
        k_gemm_s8<<<gemmBlocks, 256, GEMM_SMEM>>>(agp, hin,
                                                  wq + (long long)l * 4 * 4096,
                                                  csc + (long long)l * D,
                                                  brel + (long long)l * D, hout);
        hin = hout;
        hout = (hout == h1) ? h0 : h1;
    }

    // global mean pool
    k_zero_pool<<<(N_GRAPHS * D + 255) / 256, 256>>>();
    k_pool<<<(N_NODES + PCHUNK - 1) / PCHUNK, 128>>>(hin, bt);

    // SNN + fusion
    k_snn1<<<N_GRAPHS, 256>>>(snn_x, snn_w1, snn_b1);
    k_final<<<N_GRAPHS, 128>>>(lin_w, lin_b, snn_w2, snn_b2, fuse_w, fuse_b, out);
}

// round 12
// speedup vs baseline: 1.7640x; 1.7640x over previous
#include <cuda_runtime.h>
#include <cstdint>

#define N_NODES  100000
#define N_EDGES  1600000
#define D        128
#define N_LAYERS 7
#define N_GRAPHS 64
#define N_CLASSES 10
#define SNN_IN   512
#define SNN_HID  1024
#define SNN_BETA 0.85f

// ---------------- scratch (no allocations allowed) ----------------
__device__ float g_h0[N_NODES * D];
__device__ float g_h1[N_NODES * D];
__device__ uint32_t g_ah[N_NODES * 64];   // agg hi plane (bf16x2, 2 vals/word)
__device__ uint32_t g_al[N_NODES * 64];   // agg lo plane
__device__ int   g_counts[N_NODES];
__device__ int   g_rowptr[N_NODES + 1];
__device__ int   g_wptr[N_NODES];
__device__ int   g_esrc[N_EDGES];
__device__ int   g_blocksums[256];
__device__ float g_pool[N_GRAPHS * D];
__device__ float g_cnt[N_GRAPHS];
__device__ float g_snnh[N_GRAPHS * SNN_HID];
__device__ int   g_flags[2];   // [0]: edge_index is int64, [1]: batch is int64
// packed bf16x2 split weights: [l][mat][part][n][kword]  (2 k per word)
__device__ uint32_t g_wsp[N_LAYERS * 2 * 2 * D * (D / 2)];

// ---------------- portable tensor-core helpers (sm_80+ ISA only) ----------------
__device__ __forceinline__ uint32_t pack_bf16(float lo, float hi) {
    uint32_t r;
    asm("cvt.rn.bf16x2.f32 %0, %1, %2;" : "=r"(r) : "f"(hi), "f"(lo));
    return r;
}
__device__ __forceinline__ void mma_bf16(float* d, const uint32_t* a, uint32_t b0, uint32_t b1) {
    asm volatile(
        "mma.sync.aligned.m16n8k16.row.col.f32.bf16.bf16.f32 "
        "{%0,%1,%2,%3}, {%4,%5,%6,%7}, {%8,%9}, {%0,%1,%2,%3};"
        : "+f"(d[0]), "+f"(d[1]), "+f"(d[2]), "+f"(d[3])
        : "r"(a[0]), "r"(a[1]), "r"(a[2]), "r"(a[3]), "r"(b0), "r"(b1));
}
__device__ __forceinline__ void ldsm_x4(uint32_t* r, uint32_t addr) {
    asm volatile("ldmatrix.sync.aligned.m8n8.x4.shared.b16 {%0,%1,%2,%3}, [%4];"
        : "=r"(r[0]), "=r"(r[1]), "=r"(r[2]), "=r"(r[3]) : "r"(addr));
}
__device__ __forceinline__ uint32_t smem_u32(const void* p) {
    uint32_t a;
    asm("{ .reg .u64 t; cvta.to.shared.u64 t, %1; cvt.u32.u64 %0, t; }" : "=r"(a) : "l"(p));
    return a;
}
// split two floats into packed bf16 hi word + residual lo word
__device__ __forceinline__ void split2(float f0, float f1, uint32_t& hw, uint32_t& lw) {
    hw = pack_bf16(f0, f1);
    float f0h = __uint_as_float(hw << 16);
    float f1h = __uint_as_float(hw & 0xFFFF0000u);
    lw = pack_bf16(f0 - f0h, f1 - f1h);
}

// ---------------- index-width helpers ----------------
__device__ __forceinline__ int ld_idx(const void* p, long long i, int is64) {
    if (is64) return (int)((const long long*)p)[i];
    return ((const int*)p)[i];
}

// Parallel dtype detection
__global__ void k_detect(const unsigned int* ei, const unsigned int* bt) {
    __shared__ int e64s, b64s;
    int t = threadIdx.x;   // 256
    if (t == 0) { e64s = 1; b64s = 1; }
    __syncthreads();
    if (ei[2 * t + 1] != 0u) e64s = 0;
    if (bt[99999 - 2 * t] != 0u) b64s = 0;
    __syncthreads();
    if (t == 0) { g_flags[0] = e64s; g_flags[1] = b64s; }
}

// Transpose + bf16 hi/lo split of all layer weights, packed 2-k-per-word.
__global__ void k_wprep(const float* __restrict__ wrel, const float* __restrict__ wroot) {
    int idx = blockIdx.x * 256 + threadIdx.x;
    const int WORDS = N_LAYERS * 2 * D * (D / 2);   // 114688
    if (idx >= WORDS) return;
    int l = idx >> 14;
    int rem = idx & 16383;
    int mat = rem >> 13;
    int r2 = rem & 8191;
    int n = r2 >> 6;
    int wk = r2 & 63;
    int k = wk * 2;
    const float* W = (mat ? wroot : wrel) + (long long)l * D * D;
    float f0 = W[k * D + n];
    float f1 = W[(k + 1) * D + n];
    uint32_t hw, lw;
    split2(f0, f1, hw, lw);
    int base = ((l * 2 + mat) * 2) * 8192 + n * 64 + wk;
    g_wsp[base] = hw;
    g_wsp[base + 8192] = lw;
}

// ---------------- CSR build ----------------
__global__ void k_zero_counts() {
    int i = blockIdx.x * blockDim.x + threadIdx.x;
    if (i < N_NODES) g_counts[i] = 0;
}
__global__ void k_hist(const void* ei) {
    int e = blockIdx.x * blockDim.x + threadIdx.x;
    if (e >= N_EDGES) return;
    int dst = ld_idx(ei, (long long)N_EDGES + e, g_flags[0]);
    atomicAdd(&g_counts[dst], 1);
}
__global__ void k_scan1() {
    __shared__ int s[1024];
    int blk = blockIdx.x, t = threadIdx.x;
    int idx = blk * 1024 + t;
    int v = (idx < N_NODES) ? g_counts[idx] : 0;
    s[t] = v;
    __syncthreads();
    for (int off = 1; off < 1024; off <<= 1) {
        int add = (t >= off) ? s[t - off] : 0;
        __syncthreads();
        s[t] += add;
        __syncthreads();
    }
    if (idx < N_NODES) g_rowptr[idx] = s[t];
    if (t == 1023) g_blocksums[blk] = s[t];
}
__global__ void k_scan2(int nblocks) {
    if (blockIdx.x == 0 && threadIdx.x == 0) {
        int acc = 0;
        for (int b = 0; b < nblocks; b++) { int v = g_blocksums[b]; g_blocksums[b] = acc; acc += v; }
        g_rowptr[N_NODES] = N_EDGES;
    }
}
__global__ void k_scan3() {
    int i = blockIdx.x * blockDim.x + threadIdx.x;
    if (i < N_NODES) {
        int ex = g_rowptr[i] - g_counts[i] + g_blocksums[i >> 10];
        g_rowptr[i] = ex;
        g_wptr[i] = ex;
    }
}
__global__ void k_scatter(const void* ei) {
    int e = blockIdx.x * blockDim.x + threadIdx.x;
    if (e >= N_EDGES) return;
    int is64 = g_flags[0];
    int src = ld_idx(ei, e, is64);
    int dst = ld_idx(ei, (long long)N_EDGES + e, is64);
    int pos = atomicAdd(&g_wptr[dst], 1);
    g_esrc[pos] = src;
}

// ---------------- aggregation: warp per node, writes pre-split bf16 planes ----
__global__ void k_agg(const float* __restrict__ h,
                      uint32_t* __restrict__ aggh, uint32_t* __restrict__ aggl) {
    int node = (blockIdx.x * blockDim.x + threadIdx.x) >> 5;
    int lane = threadIdx.x & 31;
    if (node >= N_NODES) return;
    int s = g_rowptr[node];
    int e = g_rowptr[node + 1];
    float4 a0 = make_float4(0.f, 0.f, 0.f, 0.f);
    float4 a1 = make_float4(0.f, 0.f, 0.f, 0.f);
    int i = s;
    for (; i + 4 <= e; i += 4) {
        int s0 = g_esrc[i];
        int s1 = g_esrc[i + 1];
        int s2 = g_esrc[i + 2];
        int s3 = g_esrc[i + 3];
        float4 v0 = *(const float4*)&h[(long long)s0 * D + lane * 4];
        float4 v1 = *(const float4*)&h[(long long)s1 * D + lane * 4];
        float4 v2 = *(const float4*)&h[(long long)s2 * D + lane * 4];
        float4 v3 = *(const float4*)&h[(long long)s3 * D + lane * 4];
        a0.x += v0.x; a0.y += v0.y; a0.z += v0.z; a0.w += v0.w;
        a1.x += v1.x; a1.y += v1.y; a1.z += v1.z; a1.w += v1.w;
        a0.x += v2.x; a0.y += v2.y; a0.z += v2.z; a0.w += v2.w;
        a1.x += v3.x; a1.y += v3.y; a1.z += v3.z; a1.w += v3.w;
    }
    for (; i < e; i++) {
        int s0 = g_esrc[i];
        float4 v0 = *(const float4*)&h[(long long)s0 * D + lane * 4];
        a0.x += v0.x; a0.y += v0.y; a0.z += v0.z; a0.w += v0.w;
    }
    a0.x += a1.x; a0.y += a1.y; a0.z += a1.z; a0.w += a1.w;
    uint32_t h01, l01, h23, l23;
    split2(a0.x, a0.y, h01, l01);
    split2(a0.z, a0.w, h23, l23);
    *(uint2*)&aggh[(long long)node * 64 + lane * 2] = make_uint2(h01, h23);
    *(uint2*)&aggl[(long long)node * 64 + lane * 2] = make_uint2(l01, l23);
}

// ---------------- 3xBF16 mma.sync GraphConv GEMM (double-buffered) ----------------
// C[m,:] = relu( agg[m,:] @ W1 + h[m,:] @ W2 + bias )
// chunks 0..3: A = pre-split agg planes (pure copy staging)
// chunks 4..7: A = fp32 h (split on the fly). B fragments via paired ldmatrix.x4.
#define RSTR 80
#define SM_AH 0
#define SM_AL 10240
#define SM_BH 20480
#define SM_BL 30720
#define BUFSZ 40960
#define GEMM_SMEM (2 * BUFSZ)

__global__ __launch_bounds__(256, 2)
void k_gemm_bf16(const uint32_t* __restrict__ A1h, const uint32_t* __restrict__ A1l,
                 const float* __restrict__ A2,
                 const uint32_t* __restrict__ Wt,   // layer base: 4 tiles of 8192 words
                 const float* __restrict__ bias, float* __restrict__ C) {
    extern __shared__ __align__(16) char smc[];
    const uint32_t sbase = smem_u32(smc);
    const int tid = threadIdx.x;
    const int w = tid >> 5;
    const int lane = tid & 31;
    const int g = lane >> 2;
    const int tg = lane & 3;
    const int bm = blockIdx.x * 128;
    const int mbase = (w & 3) * 32;
    const int nbase = (w >> 2) * 64;

    float acc[2][8][4];
#pragma unroll
    for (int mt = 0; mt < 2; mt++)
#pragma unroll
        for (int nt = 0; nt < 8; nt++)
#pragma unroll
            for (int q = 0; q < 4; q++) acc[mt][nt][q] = 0.f;

    const int srow = tid >> 3;          // 0..31, +32 per it
    const int sq = tid & 7;             // k-quad (4 k values)

    // prefetch buffers: planes (chunks<4) or fp32 (chunks>=4)
    uint2 ph[4], pl[4];
    float4 pf[4];

    // ---- prologue: load + stage chunk 0 (agg planes) into buf0 ----
#pragma unroll
    for (int it = 0; it < 4; it++) {
        int row = it * 32 + srow;
        if (bm + row < N_NODES) {
            ph[it] = *(const uint2*)&A1h[(long long)(bm + row) * 64 + sq * 2];
            pl[it] = *(const uint2*)&A1l[(long long)(bm + row) * 64 + sq * 2];
        } else {
            ph[it] = make_uint2(0u, 0u);
            pl[it] = make_uint2(0u, 0u);
        }
    }
#pragma unroll
    for (int it = 0; it < 4; it++) {
        int row = it * 32 + srow;
        uint32_t off = (uint32_t)(row * RSTR + sq * 8);
        *(uint2*)(smc + SM_AH + off) = ph[it];
        *(uint2*)(smc + SM_AL + off) = pl[it];
        *(uint2*)(smc + SM_BH + off) = *(const uint2*)&Wt[row * 64 + sq * 2];
        *(uint2*)(smc + SM_BL + off) = *(const uint2*)&Wt[8192 + row * 64 + sq * 2];
    }
    __syncthreads();
    // prefetch chunk 1 (agg planes)
#pragma unroll
    for (int it = 0; it < 4; it++) {
        int row = it * 32 + srow;
        if (bm + row < N_NODES) {
            ph[it] = *(const uint2*)&A1h[(long long)(bm + row) * 64 + 16 + sq * 2];
            pl[it] = *(const uint2*)&A1l[(long long)(bm + row) * 64 + 16 + sq * 2];
        } else {
            ph[it] = make_uint2(0u, 0u);
            pl[it] = make_uint2(0u, 0u);
        }
    }

    // ldmatrix lane addressing
    const int aRow16 = lane & 15;
    const uint32_t aSel = (uint32_t)(lane >> 4) * 16u;
    const int bRowP = (lane & 7) + ((lane >> 4) << 3);     // +8 rows for lanes 16-31
    const uint32_t bK = (uint32_t)((lane >> 3) & 1) * 16u;

#pragma unroll
    for (int c = 0; c < 8; c++) {
        const uint32_t curB = (uint32_t)(c & 1) * BUFSZ;
        const uint32_t nxtB = curB ^ BUFSZ;

        // ---- stage chunk c+1 into buf[nxt] ----
        if (c < 7) {
            const int cn = c + 1;
            const int k0w = (cn & 3) * 16;
            const uint32_t* Whi = Wt + ((cn >> 2) * 2) * 8192;
            const uint32_t* Wlo = Whi + 8192;
#pragma unroll
            for (int it = 0; it < 4; it++) {
                int row = it * 32 + srow;
                uint32_t off = nxtB + (uint32_t)(row * RSTR + sq * 8);
                if (cn < 4) {
                    *(uint2*)(smc + SM_AH + off) = ph[it];
                    *(uint2*)(smc + SM_AL + off) = pl[it];
                } else {
                    float4 v = pf[it];
                    uint32_t h01, l01, h23, l23;
                    split2(v.x, v.y, h01, l01);
                    split2(v.z, v.w, h23, l23);
                    *(uint2*)(smc + SM_AH + off) = make_uint2(h01, h23);
                    *(uint2*)(smc + SM_AL + off) = make_uint2(l01, l23);
                }
                *(uint2*)(smc + SM_BH + off) = *(const uint2*)&Whi[row * 64 + k0w + sq * 2];
                *(uint2*)(smc + SM_BL + off) = *(const uint2*)&Wlo[row * 64 + k0w + sq * 2];
            }
        }
        // ---- prefetch chunk c+2 ----
        if (c < 6) {
            const int cn2 = c + 2;
#pragma unroll
            for (int it = 0; it < 4; it++) {
                int row = it * 32 + srow;
                if (cn2 < 4) {
                    if (bm + row < N_NODES) {
                        ph[it] = *(const uint2*)&A1h[(long long)(bm + row) * 64 + cn2 * 16 + sq * 2];
                        pl[it] = *(const uint2*)&A1l[(long long)(bm + row) * 64 + cn2 * 16 + sq * 2];
                    } else {
                        ph[it] = make_uint2(0u, 0u);
                        pl[it] = make_uint2(0u, 0u);
                    }
                } else {
                    const int k0n = (cn2 & 3) * 32;
                    pf[it] = (bm + row < N_NODES)
                             ? *(const float4*)&A2[(long long)(bm + row) * 128 + k0n + sq * 4]
                             : make_float4(0.f, 0.f, 0.f, 0.f);
                }
            }
        }

        // ---- compute chunk c: 2 k16-steps, B via paired x4 ----
#pragma unroll
        for (int ks = 0; ks < 2; ks++) {
            uint32_t ah[2][4], al[2][4];
#pragma unroll
            for (int mt = 0; mt < 2; mt++) {
                uint32_t base = sbase + curB + (uint32_t)((mbase + mt * 16 + aRow16) * RSTR)
                              + (uint32_t)ks * 32u + aSel;
                ldsm_x4(ah[mt], base + SM_AH);
                ldsm_x4(al[mt], base + SM_AL);
            }
#pragma unroll
            for (int ntp = 0; ntp < 4; ntp++) {
                uint32_t bb = sbase + curB + (uint32_t)((nbase + ntp * 16 + bRowP) * RSTR)
                            + (uint32_t)ks * 32u + bK;
                uint32_t bh[4], bl[4];
                ldsm_x4(bh, bb + SM_BH);
                ldsm_x4(bl, bb + SM_BL);
                const int nt0 = 2 * ntp;
                const int nt1 = nt0 + 1;
#pragma unroll
                for (int mt = 0; mt < 2; mt++) {
                    mma_bf16(acc[mt][nt0], ah[mt], bh[0], bh[1]);
                    mma_bf16(acc[mt][nt0], ah[mt], bl[0], bl[1]);
                    mma_bf16(acc[mt][nt0], al[mt], bh[0], bh[1]);
                    mma_bf16(acc[mt][nt1], ah[mt], bh[2], bh[3]);
                    mma_bf16(acc[mt][nt1], ah[mt], bl[2], bl[3]);
                    mma_bf16(acc[mt][nt1], al[mt], bh[2], bh[3]);
                }
            }
        }
        __syncthreads();
    }

    // ---- epilogue: bias + relu, float2 stores ----
#pragma unroll
    for (int mt = 0; mt < 2; mt++) {
        int row0 = bm + mbase + mt * 16 + g;
        int row1 = row0 + 8;
#pragma unroll
        for (int nt = 0; nt < 8; nt++) {
            int col = nbase + nt * 8 + 2 * tg;
            float b0 = bias[col];
            float b1 = bias[col + 1];
            if (row0 < N_NODES) {
                float2 o;
                o.x = fmaxf(acc[mt][nt][0] + b0, 0.f);
                o.y = fmaxf(acc[mt][nt][1] + b1, 0.f);
                *(float2*)&C[(long long)row0 * 128 + col] = o;
            }
            if (row1 < N_NODES) {
                float2 o;
                o.x = fmaxf(acc[mt][nt][2] + b0, 0.f);
                o.y = fmaxf(acc[mt][nt][3] + b1, 0.f);
                *(float2*)&C[(long long)row1 * 128 + col] = o;
            }
        }
    }
}

// ---------------- pooling / SNN / fusion ----------------
__global__ void k_zero_pool() {
    int i = blockIdx.x * blockDim.x + threadIdx.x;
    if (i < N_GRAPHS * D) g_pool[i] = 0.f;
    if (i < N_GRAPHS) g_cnt[i] = 0.f;
}

#define PCHUNK 256
__global__ void k_pool(const float* __restrict__ h, const void* bt) {
    int blk = blockIdx.x;
    int f = threadIdx.x;
    int start = blk * PCHUNK;
    if (start >= N_NODES) return;
    int end = start + PCHUNK;
    if (end > N_NODES) end = N_NODES;
    int is64 = g_flags[1];
    int cur = ld_idx(bt, start, is64);
    float s = 0.f, c = 0.f;
    for (int n = start; n < end; n++) {
        int g = ld_idx(bt, n, is64);
        if (g != cur) {
            atomicAdd(&g_pool[cur * D + f], s);
            if (f == 0) atomicAdd(&g_cnt[cur], c);
            s = 0.f; c = 0.f; cur = g;
        }
        s += h[(long long)n * D + f];
        c += 1.f;
    }
    atomicAdd(&g_pool[cur * D + f], s);
    if (f == 0) atomicAdd(&g_cnt[cur], c);
}

__global__ void k_snn1(const float* __restrict__ x, const float* __restrict__ w1,
                       const float* __restrict__ b1) {
    int g = blockIdx.x;
    int t = threadIdx.x;   // 256
    __shared__ float xs[SNN_IN];
    for (int i = t; i < SNN_IN; i += 256) xs[i] = x[g * SNN_IN + i];
    __syncthreads();
    for (int j = t; j < SNN_HID; j += 256) {
        float a = b1[j];
        for (int k = 0; k < SNN_IN; k++)
            a += xs[k] * w1[k * SNN_HID + j];
        g_snnh[g * SNN_HID + j] = fmaxf(a, 0.f);
    }
}

__global__ void k_final(const float* __restrict__ lin_w, const float* __restrict__ lin_b,
                        const float* __restrict__ w2, const float* __restrict__ b2,
                        const float* __restrict__ fuse_w, const float* __restrict__ fuse_b,
                        float* __restrict__ out) {
    int g = blockIdx.x;
    int t = threadIdx.x;   // 128
    __shared__ float mean[D];
    __shared__ float red[128];
    __shared__ float snl[N_CLASSES], gnl[N_CLASSES];
    float cnt = fmaxf(g_cnt[g], 1.f);
    mean[t] = g_pool[g * D + t] / cnt;
    __syncthreads();
    for (int c = 0; c < N_CLASSES; c++) {
        red[t] = mean[t] * lin_w[t * N_CLASSES + c];
        for (int off = 64; off > 0; off >>= 1) {
            __syncthreads();
            if (t < off) red[t] += red[t + off];
        }
        __syncthreads();
        if (t == 0) gnl[c] = red[0] + lin_b[c];
        __syncthreads();
    }
    for (int c = 0; c < N_CLASSES; c++) {
        float p = 0.f;
        for (int k = t; k < SNN_HID; k += 128)
            p += g_snnh[g * SNN_HID + k] * w2[k * N_CLASSES + c];
        red[t] = p;
        for (int off = 64; off > 0; off >>= 1) {
            __syncthreads();
            if (t < off) red[t] += red[t + off];
        }
        __syncthreads();
        if (t == 0) snl[c] = SNN_BETA * (red[0] + b2[c]);
        __syncthreads();
    }
    if (t < N_CLASSES) {
        float o = fuse_b[t];
        for (int j = 0; j < N_CLASSES; j++) {
            o += snl[j] * fuse_w[j * N_CLASSES + t];
            o += gnl[j] * fuse_w[(N_CLASSES + j) * N_CLASSES + t];
        }
        out[g * N_CLASSES + t] = o;
    }
}

// ---------------- launch ----------------
extern "C" void kernel_launch(void* const* d_in, const int* in_sizes, int n_in,
                              void* d_out, int out_size) {
    const float* snn_x  = (const float*)d_in[0];
    const float* x      = (const float*)d_in[1];
    const void*  ei     = d_in[2];
    const void*  bt     = d_in[3];
    const float* snn_w1 = (const float*)d_in[4];
    const float* snn_b1 = (const float*)d_in[5];
    const float* snn_w2 = (const float*)d_in[6];
    const float* snn_b2 = (const float*)d_in[7];
    const float* wrel   = (const float*)d_in[8];
    const float* wroot  = (const float*)d_in[9];
    const float* brel   = (const float*)d_in[10];
    const float* lin_w  = (const float*)d_in[11];
    const float* lin_b  = (const float*)d_in[12];
    const float* fuse_w = (const float*)d_in[13];
    const float* fuse_b = (const float*)d_in[14];
    float* out = (float*)d_out;

    void* p;
    cudaGetSymbolAddress(&p, g_h0);   float* h0  = (float*)p;
    cudaGetSymbolAddress(&p, g_h1);   float* h1  = (float*)p;
    cudaGetSymbolAddress(&p, g_ah);   uint32_t* ah = (uint32_t*)p;
    cudaGetSymbolAddress(&p, g_al);   uint32_t* al = (uint32_t*)p;
    cudaGetSymbolAddress(&p, g_wsp);  uint32_t* wsp = (uint32_t*)p;

    cudaFuncSetAttribute(k_gemm_bf16, cudaFuncAttributeMaxDynamicSharedMemorySize, GEMM_SMEM);

    k_detect<<<1, 256>>>((const unsigned int*)ei, (const unsigned int*)bt);
    k_wprep<<<(N_LAYERS * 2 * D * (D / 2) + 255) / 256, 256>>>(wrel, wroot);

    // CSR build (by dst)
    k_zero_counts<<<(N_NODES + 255) / 256, 256>>>();
    k_hist<<<(N_EDGES + 255) / 256, 256>>>(ei);
    const int nsb = (N_NODES + 1023) / 1024;   // 98
    k_scan1<<<nsb, 1024>>>();
    k_scan2<<<1, 1>>>(nsb);
    k_scan3<<<(N_NODES + 255) / 256, 256>>>();
    k_scatter<<<(N_EDGES + 255) / 256, 256>>>(ei);

    // 7 GraphConv layers; layer 0 consumes x directly
    const float* hin = x;
    float* hout = h1;
    const int aggBlocks = (N_NODES * 32 + 255) / 256;
    const int gemmBlocks = (N_NODES + 127) / 128;   // 782
    for (int l = 0; l < N_LAYERS; l++) {
        k_agg<<<aggBlocks, 256>>>(hin, ah, al);
        k_gemm_bf16<<<gemmBlocks, 256, GEMM_SMEM>>>(ah, al, hin,
                                                    wsp + (long long)l * 4 * 8192,
                                                    brel + (long long)l * D, hout);
        hin = hout;
        hout = (hout == h1) ? h0 : h1;
    }

    // global mean pool
    k_zero_pool<<<(N_GRAPHS * D + 255) / 256, 256>>>();
    k_pool<<<(N_NODES + PCHUNK - 1) / PCHUNK, 128>>>(hin, bt);

    // SNN + fusion
    k_snn1<<<N_GRAPHS, 256>>>(snn_x, snn_w1, snn_b1);
    k_final<<<N_GRAPHS, 128>>>(lin_w, lin_b, snn_w2, snn_b2, fuse_w, fuse_b, out);
}